// round 2
// baseline (speedup 1.0000x reference)
#include <cuda_runtime.h>
#include <math.h>

// ---------------------------------------------------------------------------
// Style2ResidualBlock1DSrc: modulated conv1d, restructured as
//   s[b,i]      = style_b[i] + LIN_SCALE * (concat(c_src,c_trg)[b] . style_w[i])
//   demod[b,o]  = rsqrt(CONV_SCALE^2 * sum_i (sum_k weight[o,i,k]^2) s[b,i]^2 + 1e-8)
//   out[b,o,t]  = CONV_SCALE*demod[b,o] * sum_{i,k} weight[o,i,k]*s[b,i]*x[b,i,t+k-1]
// Heavy op = 16 batched implicit-im2col GEMMs done with packed f32x2 FMA.
// ---------------------------------------------------------------------------

#define B_      16
#define CIN     512
#define COUT    512
#define T_      2048
#define KW      3

#define LIN_SCALE  0.0625f                    // 1/sqrt(256)
#define CONV_SCALE 1.4731391274719738e-2f     // 1/sqrt(512*9)
#define CONV_SCALE2 (1.0f/4608.0f)

// Scratch (device globals: allocation-free rule)
__device__ float g_s[B_ * CIN];           // style codes
__device__ float g_demod[B_ * COUT];      // demod factors
__device__ float g_wt[CIN * KW * COUT];   // weight transposed to [i][k][o]

// ---- packed f32x2 helpers (FFMA2 only reachable via inline PTX) ----
#define FMA2(d, a, b, c) \
    asm("fma.rn.f32x2 %0, %1, %2, %3;" : "=l"(d) : "l"(a), "l"(b), "l"(c))
#define PACK_DUP(d, f) \
    asm("mov.b64 %0, {%1, %1};" : "=l"(d) : "f"(f))
#define UNPACK2(lo, hi, v) \
    asm("mov.b64 {%0, %1}, %2;" : "=f"(lo), "=f"(hi) : "l"(v))

// ---------------------------------------------------------------------------
// Kernel 1: style codes s[b,i]
// ---------------------------------------------------------------------------
__global__ void style_kernel(const float* __restrict__ c_src,
                             const float* __restrict__ c_trg,
                             const float* __restrict__ style_w,
                             const float* __restrict__ style_b)
{
    int b = blockIdx.x;
    int i = threadIdx.x;            // 512 threads
    __shared__ float c[256];
    if (i < 128)       c[i] = c_src[b * 128 + i];
    else if (i < 256)  c[i] = c_trg[b * 128 + (i - 128)];
    __syncthreads();

    const float* row = style_w + (size_t)i * 256;
    float acc = 0.f;
#pragma unroll 8
    for (int j = 0; j < 256; j++) acc += row[j] * c[j];
    g_s[b * CIN + i] = style_b[i] + LIN_SCALE * acc;
}

// ---------------------------------------------------------------------------
// Kernel 2: transpose weight [o][i][k] -> g_wt[(i*3+k)*512 + o]
// ---------------------------------------------------------------------------
__global__ void trans_kernel(const float* __restrict__ weight)
{
    int idx = blockIdx.x * 256 + threadIdx.x;   // 786432 total
    if (idx >= CIN * KW * COUT) return;
    int o   = idx & (COUT - 1);
    int ik  = idx >> 9;          // 0..1535
    int k   = ik % 3;
    int i   = ik / 3;
    g_wt[idx] = weight[(size_t)o * (CIN * KW) + i * KW + k];
}

// ---------------------------------------------------------------------------
// Kernel 3: demod[b,o]
// One block (256 thr) per o; accumulates over i for all 16 b at once.
// ---------------------------------------------------------------------------
__global__ void demod_kernel(const float* __restrict__ weight)
{
    int o   = blockIdx.x;
    int tid = threadIdx.x;

    float acc[B_];
#pragma unroll
    for (int b = 0; b < B_; b++) acc[b] = 0.f;

    for (int i = tid; i < CIN; i += 256) {
        const float* wp = weight + (size_t)o * (CIN * KW) + i * KW;
        float w0 = wp[0], w1 = wp[1], w2 = wp[2];
        float wsq = w0 * w0 + w1 * w1 + w2 * w2;
#pragma unroll
        for (int b = 0; b < B_; b++) {
            float sv = g_s[b * CIN + i];
            acc[b] += wsq * sv * sv;
        }
    }
    // warp reduce
#pragma unroll
    for (int b = 0; b < B_; b++)
#pragma unroll
        for (int off = 16; off; off >>= 1)
            acc[b] += __shfl_down_sync(0xffffffffu, acc[b], off);

    __shared__ float red[8][B_];
    int lane = tid & 31, warp = tid >> 5;
    if (lane == 0)
#pragma unroll
        for (int b = 0; b < B_; b++) red[warp][b] = acc[b];
    __syncthreads();

    if (tid < B_) {
        float t = 0.f;
#pragma unroll
        for (int w = 0; w < 8; w++) t += red[w][tid];
        g_demod[tid * COUT + o] = rsqrtf(CONV_SCALE2 * t + 1e-8f);
    }
}

// ---------------------------------------------------------------------------
// Kernel 4: main conv. 128(o) x 128(t) tile per CTA, 8x8 per thread held as
// 4 o-pairs x 8 t in packed f32x2 accumulators. I-chunk = 16.
// ---------------------------------------------------------------------------
#define I_BLK 16
#define O_BLK 128
#define T_BLK 128
#define XROW  132   // 130 used, padded to keep 16B alignment

__global__ __launch_bounds__(256, 2)
void conv_kernel(const float* __restrict__ x, float* __restrict__ out)
{
    __shared__ float Xs[I_BLK][XROW];
    __shared__ float Ws[I_BLK][KW][O_BLK];

    int b  = blockIdx.z;
    int o0 = blockIdx.y * O_BLK;
    int t0 = blockIdx.x * T_BLK;
    int tid = threadIdx.x;
    int tx = tid & 15;   // t micro-tile
    int ty = tid >> 4;   // o micro-tile

    const float* xb = x + (size_t)b * CIN * T_;

    unsigned long long acc[4][8];
#pragma unroll
    for (int p = 0; p < 4; p++)
#pragma unroll
        for (int tt = 0; tt < 8; tt++) acc[p][tt] = 0ull;

    for (int i0 = 0; i0 < CIN; i0 += I_BLK) {
        // --- load modulated x tile: 16 x 130 (t0-1 .. t0+128) ---
        for (int idx = tid; idx < I_BLK * 130; idx += 256) {
            int i  = idx / 130;
            int tt = idx - i * 130;
            int tg = t0 + tt - 1;
            float v = 0.f;
            if (tg >= 0 && tg < T_) {
                float sv = g_s[b * CIN + i0 + i];
                v = xb[(size_t)(i0 + i) * T_ + tg] * sv;
            }
            Xs[i][tt] = v;
        }
        // --- load weight tile: [i][k][o], o contiguous (coalesced from g_wt) ---
        for (int idx = tid; idx < I_BLK * KW * O_BLK; idx += 256) {
            int o    = idx & (O_BLK - 1);
            int rest = idx >> 7;
            int k    = rest % 3;
            int i    = rest / 3;
            Ws[i][k][o] = g_wt[(size_t)((i0 + i) * KW + k) * COUT + o0 + o];
        }
        __syncthreads();

#pragma unroll 4
        for (int i = 0; i < I_BLK; i++) {
            float xr[10];
            float4 xa = *(const float4*)&Xs[i][tx * 8];
            float4 xb4 = *(const float4*)&Xs[i][tx * 8 + 4];
            xr[0] = xa.x; xr[1] = xa.y; xr[2] = xa.z; xr[3] = xa.w;
            xr[4] = xb4.x; xr[5] = xb4.y; xr[6] = xb4.z; xr[7] = xb4.w;
            xr[8] = Xs[i][tx * 8 + 8];
            xr[9] = Xs[i][tx * 8 + 9];

            unsigned long long xd[10];
#pragma unroll
            for (int d = 0; d < 10; d++) PACK_DUP(xd[d], xr[d]);

#pragma unroll
            for (int k = 0; k < KW; k++) {
                unsigned long long wv[4];
#pragma unroll
                for (int p = 0; p < 4; p++)
                    wv[p] = *(const unsigned long long*)&Ws[i][k][ty * 8 + 2 * p];
#pragma unroll
                for (int p = 0; p < 4; p++)
#pragma unroll
                    for (int tt = 0; tt < 8; tt++)
                        FMA2(acc[p][tt], wv[p], xd[tt + k], acc[p][tt]);
            }
        }
        __syncthreads();
    }

    // --- epilogue: scale by CONV_SCALE*demod and store ---
#pragma unroll
    for (int p = 0; p < 4; p++) {
        float r0[8], r1[8];
#pragma unroll
        for (int tt = 0; tt < 8; tt++) UNPACK2(r0[tt], r1[tt], acc[p][tt]);

        int orow = o0 + ty * 8 + 2 * p;
        float s0 = CONV_SCALE * g_demod[b * COUT + orow];
        float s1 = CONV_SCALE * g_demod[b * COUT + orow + 1];

        float* p0 = out + ((size_t)(b * COUT + orow)) * T_ + t0 + tx * 8;
        float* p1 = p0 + T_;

        float4 a0 = make_float4(r0[0]*s0, r0[1]*s0, r0[2]*s0, r0[3]*s0);
        float4 a1 = make_float4(r0[4]*s0, r0[5]*s0, r0[6]*s0, r0[7]*s0);
        float4 b0 = make_float4(r1[0]*s1, r1[1]*s1, r1[2]*s1, r1[3]*s1);
        float4 b1 = make_float4(r1[4]*s1, r1[5]*s1, r1[6]*s1, r1[7]*s1);
        *(float4*)p0       = a0;
        *(float4*)(p0 + 4) = a1;
        *(float4*)p1       = b0;
        *(float4*)(p1 + 4) = b1;
    }
}

// ---------------------------------------------------------------------------
extern "C" void kernel_launch(void* const* d_in, const int* in_sizes, int n_in,
                              void* d_out, int out_size)
{
    const float* x       = (const float*)d_in[0];
    const float* c_src   = (const float*)d_in[1];
    const float* c_trg   = (const float*)d_in[2];
    const float* style_w = (const float*)d_in[3];
    const float* style_b = (const float*)d_in[4];
    const float* weight  = (const float*)d_in[5];
    float* out = (float*)d_out;

    style_kernel<<<B_, 512>>>(c_src, c_trg, style_w, style_b);
    trans_kernel<<<(CIN * KW * COUT + 255) / 256, 256>>>(weight);
    demod_kernel<<<COUT, 256>>>(weight);
    conv_kernel<<<dim3(T_ / T_BLK, COUT / O_BLK, B_), 256>>>(x, out);
}

// round 5
// speedup vs baseline: 2.8196x; 2.8196x over previous
#include <cuda_runtime.h>
#include <cuda_bf16.h>
#include <math.h>
#include <stdint.h>

#define B_      16
#define CIN     512
#define COUT    512
#define T_      2048
#define KW      3
#define LIN_SCALE  0.0625f
#define CONV_SCALE 1.4731391274719738e-2f
#define CONV_SCALE2 (1.0f/4608.0f)

#define NCH     16                 // K chunks (512 / 32)
#define XROWS   136                // B tile rows: t0-1 .. t0+134
#define ROWB    80                 // padded row stride (5*16B -> conflict-free ldmatrix)
#define A_TILE  (128 * ROWB)       // 10240 B
#define B_TILE  (XROWS * ROWB)     // 10880 B
#define STAGE   (6 * A_TILE + 2 * B_TILE)   // 83200 B
#define NSTG    2
#define SMEM_TOTAL (1024 + NSTG * STAGE)    // 167424 B

// ---- device scratch (allocation-free rule) ----
__device__ float g_s[B_ * CIN];
__device__ float g_demod[B_ * COUT];
// W images: [((k*2+p)*4 + ot)*16 + ch] tiles of 128 x 80B   (~7.9 MB)
__device__ __align__(1024) char g_Wimg[3 * 2 * 4 * NCH * A_TILE];
// X images: [((b*16+tt)*2 + p)*16 + ch] tiles of 136 x 80B  (~89 MB)
__device__ __align__(1024) char g_Ximg[(size_t)B_ * 16 * 2 * NCH * B_TILE];

// ---------------- PTX helpers (compute_103-safe) ----------------
__device__ __forceinline__ uint32_t smem_u32(const void* p) {
    uint32_t a;
    asm("{ .reg .u64 t; cvta.to.shared.u64 t, %1; cvt.u32.u64 %0, t; }" : "=r"(a) : "l"(p));
    return a;
}
__device__ __forceinline__ uint32_t elect_one() {
    uint32_t p;
    asm volatile("{ .reg .pred p; elect.sync _|p, 0xFFFFFFFF; selp.b32 %0,1,0,p; }" : "=r"(p));
    return p;
}
#define MBAR_INIT(a, n) \
    asm volatile("mbarrier.init.shared.b64 [%0], %1;" :: "r"(a), "r"((uint32_t)(n)) : "memory")
#define MBAR_EXPECT_TX(a, n) \
    asm volatile("mbarrier.arrive.expect_tx.shared.b64 _, [%0], %1;" :: "r"(a), "r"((uint32_t)(n)) : "memory")
#define MBAR_ARRIVE(a) \
    asm volatile("mbarrier.arrive.shared.b64 _, [%0];" :: "r"(a) : "memory")
#define MBAR_WAIT(a, ph) do {                                                  \
    uint32_t _m = (a), _p = (ph), _d;                                          \
    asm volatile("{ .reg .pred p; mbarrier.try_wait.parity.acquire.cta.shared::cta.b64 p, [%1], %2; selp.b32 %0,1,0,p; }" \
                 : "=r"(_d) : "r"(_m), "r"(_p) : "memory");                    \
    if (!_d) {                                                                 \
        asm volatile("{ .reg .pred P1; WL%=: mbarrier.try_wait.parity.acquire.cta.shared::cta.b64 P1, [%0], %1, 0x989680; @P1 bra.uni WD%=; bra.uni WL%=; WD%=: }" \
                     :: "r"(_m), "r"(_p) : "memory");                          \
    } } while (0)
#define BULK_CP(dst, src, nb, mb)                                              \
    asm volatile("cp.async.bulk.shared::cta.global.mbarrier::complete_tx::bytes [%0], [%1], %2, [%3];" \
                 :: "r"((uint32_t)(dst)), "l"(src), "r"((uint32_t)(nb)), "r"((uint32_t)(mb)) : "memory")

#define LDSM_X4(r, addr) \
    asm volatile("ldmatrix.sync.aligned.m8n8.x4.shared.b16 {%0,%1,%2,%3}, [%4];" \
        : "=r"((r)[0]), "=r"((r)[1]), "=r"((r)[2]), "=r"((r)[3]) : "r"(addr))
#define LDSM_X2(r, addr) \
    asm volatile("ldmatrix.sync.aligned.m8n8.x2.shared.b16 {%0,%1}, [%2];" \
        : "=r"((r)[0]), "=r"((r)[1]) : "r"(addr))
#define MMA(c, a, b)                                                           \
    asm volatile("mma.sync.aligned.m16n8k16.row.col.f32.bf16.bf16.f32 "        \
        "{%0,%1,%2,%3}, {%4,%5,%6,%7}, {%8,%9}, {%0,%1,%2,%3};"                \
        : "+f"((c)[0]), "+f"((c)[1]), "+f"((c)[2]), "+f"((c)[3])               \
        : "r"((a)[0]), "r"((a)[1]), "r"((a)[2]), "r"((a)[3]),                  \
          "r"((b)[0]), "r"((b)[1]))

// ---------------- prep kernels ----------------
__global__ void style_kernel(const float* __restrict__ c_src, const float* __restrict__ c_trg,
                             const float* __restrict__ style_w, const float* __restrict__ style_b)
{
    int b = blockIdx.x, i = threadIdx.x;
    __shared__ float c[256];
    if (i < 128)      c[i] = c_src[b * 128 + i];
    else if (i < 256) c[i] = c_trg[b * 128 + (i - 128)];
    __syncthreads();
    const float* row = style_w + (size_t)i * 256;
    float acc = 0.f;
#pragma unroll 8
    for (int j = 0; j < 256; j++) acc += row[j] * c[j];
    g_s[b * CIN + i] = style_b[i] + LIN_SCALE * acc;
}

__global__ void demod_kernel(const float* __restrict__ weight)
{
    int o = blockIdx.x, tid = threadIdx.x;
    float acc[B_];
#pragma unroll
    for (int b = 0; b < B_; b++) acc[b] = 0.f;
    for (int i = tid; i < CIN; i += 256) {
        const float* wp = weight + (size_t)o * (CIN * KW) + i * KW;
        float w0 = wp[0], w1 = wp[1], w2 = wp[2];
        float wsq = w0*w0 + w1*w1 + w2*w2;
#pragma unroll
        for (int b = 0; b < B_; b++) { float sv = g_s[b * CIN + i]; acc[b] += wsq * sv * sv; }
    }
#pragma unroll
    for (int b = 0; b < B_; b++)
#pragma unroll
        for (int off = 16; off; off >>= 1)
            acc[b] += __shfl_down_sync(0xffffffffu, acc[b], off);
    __shared__ float red[8][B_];
    int lane = tid & 31, warp = tid >> 5;
    if (lane == 0)
#pragma unroll
        for (int b = 0; b < B_; b++) red[warp][b] = acc[b];
    __syncthreads();
    if (tid < B_) {
        float t = 0.f;
#pragma unroll
        for (int w = 0; w < 8; w++) t += red[w][tid];
        g_demod[tid * COUT + o] = rsqrtf(CONV_SCALE2 * t + 1e-8f);
    }
}

// weight[o][i][k] -> A tile images (hi/lo bf16 split), rows=o (80B stride), cols=i
__global__ void prepw_kernel(const float* __restrict__ weight)
{
    int idx = blockIdx.x * 256 + threadIdx.x;
    if (idx >= KW * COUT * CIN) return;
    int i = idx & (CIN - 1);
    int o = (idx >> 9) & (COUT - 1);
    int k = idx >> 18;
    float v = weight[((size_t)o * CIN + i) * KW + k];
    __nv_bfloat16 hb = __float2bfloat16(v);
    float hf = __bfloat162float(hb);
    __nv_bfloat16 lb = __float2bfloat16(v - hf);
    int ot = o >> 7, row = o & 127, ch = i >> 5, il = i & 31;
    size_t off = (size_t)row * ROWB + il * 2;
    size_t th = (size_t)(((k * 2 + 0) * 4 + ot) * NCH + ch) * A_TILE;
    size_t tl = (size_t)(((k * 2 + 1) * 4 + ot) * NCH + ch) * A_TILE;
    *(uint16_t*)(g_Wimg + th + off) = *(uint16_t*)&hb;
    *(uint16_t*)(g_Wimg + tl + off) = *(uint16_t*)&lb;
}

// x[b][i][t]*s -> B tile images (hi/lo), rows=t (t0-1..t0+134, 80B stride), cols=i
__global__ void prepx_kernel(const float* __restrict__ x)
{
    int ch = blockIdx.x, tt = blockIdx.y, b = blockIdx.z;
    int tid = threadIdx.x, i0 = ch * 32, tbase = tt * 128 - 1;
    __shared__ float tile[32][XROWS];
    for (int idx = tid; idx < 32 * XROWS; idx += 256) {
        int i = idx / XROWS, r = idx - i * XROWS, tg = tbase + r;
        float v = 0.f;
        if (tg >= 0 && tg < T_)
            v = x[((size_t)b * CIN + i0 + i) * T_ + tg] * g_s[b * CIN + i0 + i];
        tile[i][r] = v;
    }
    __syncthreads();
    char* dh = g_Ximg + (size_t)(((b * 16 + tt) * 2 + 0) * NCH + ch) * B_TILE;
    char* dl = g_Ximg + (size_t)(((b * 16 + tt) * 2 + 1) * NCH + ch) * B_TILE;
    for (int idx = tid; idx < XROWS * 16; idx += 256) {
        int r = idx >> 4, dp = idx & 15;
        float v0 = tile[dp * 2][r], v1 = tile[dp * 2 + 1][r];
        uint32_t hp;
        asm("cvt.rn.bf16x2.f32 %0, %1, %2;" : "=r"(hp) : "f"(v1), "f"(v0));
        float h0 = __uint_as_float(hp << 16);
        float h1 = __uint_as_float(hp & 0xFFFF0000u);
        uint32_t lp;
        asm("cvt.rn.bf16x2.f32 %0, %1, %2;" : "=r"(lp) : "f"(v1 - h1), "f"(v0 - h0));
        *(uint32_t*)(dh + r * ROWB + dp * 4) = hp;
        *(uint32_t*)(dl + r * ROWB + dp * 4) = lp;
    }
}

// ---------------- main GEMM kernel ----------------
// 9 warps: 0-7 compute (2x4 warp grid, m64n32 each), 8 = bulk-copy producer.
// mbarriers: full[st] at sb+0/8 (count 1, tx); empty[st] at sb+16/24 (count 8).
__global__ void __launch_bounds__(288, 1)
gemm_kernel(float* __restrict__ out)
{
    extern __shared__ __align__(1024) char smem[];
    const uint32_t sb = smem_u32(smem);
    int tid = threadIdx.x, wid = tid >> 5, lane = tid & 31;
    int tt = blockIdx.x, ot = blockIdx.y, b = blockIdx.z;

    if (tid == 0) {
        MBAR_INIT(sb + 0, 1);  MBAR_INIT(sb + 8, 1);
        MBAR_INIT(sb + 16, 8); MBAR_INIT(sb + 24, 8);
    }
    __syncthreads();

    if (wid == 8) {
        if (elect_one()) {
            for (int cc = 0; cc < 8; cc++) {
#pragma unroll
                for (int st = 0; st < 2; st++) {
                    int c = cc * 2 + st;
                    MBAR_WAIT(sb + 16 + st * 8, (cc & 1) ^ 1);
                    MBAR_EXPECT_TX(sb + st * 8, STAGE);
                    uint32_t dbase = sb + 1024 + st * STAGE;
#pragma unroll
                    for (int kp = 0; kp < 6; kp++) {
                        const char* src = g_Wimg + (size_t)((kp * 4 + ot) * NCH + c) * A_TILE;
                        BULK_CP(dbase + kp * A_TILE, src, A_TILE, sb + st * 8);
                    }
#pragma unroll
                    for (int p = 0; p < 2; p++) {
                        const char* src = g_Ximg + (size_t)(((b * 16 + tt) * 2 + p) * NCH + c) * B_TILE;
                        BULK_CP(dbase + 6 * A_TILE + p * B_TILE, src, B_TILE, sb + st * 8);
                    }
                }
            }
        }
    } else {
        int wo = wid >> 2;          // 0..1  (o half)
        int wt = wid & 3;           // 0..3  (t quarter)
        float acc[4][4][4];
#pragma unroll
        for (int mt = 0; mt < 4; mt++)
#pragma unroll
            for (int nt = 0; nt < 4; nt++)
#pragma unroll
                for (int e = 0; e < 4; e++) acc[mt][nt][e] = 0.f;

        // ldmatrix per-lane offsets
        const uint32_t aoff = (uint32_t)((wo * 64 + (lane & 15)) * ROWB + (lane >> 4) * 16);
        const int lr = lane & 15;
        const uint32_t boff = (uint32_t)((wt * 32 + (lr & 7)) * ROWB + (lr >> 3) * 16);

        for (int cc = 0; cc < 8; cc++) {
#pragma unroll
            for (int st = 0; st < 2; st++) {
                MBAR_WAIT(sb + st * 8, cc & 1);
                const uint32_t base = sb + 1024 + st * STAGE;
#pragma unroll
                for (int s = 0; s < 2; s++) {
#pragma unroll
                    for (int k = 0; k < 3; k++) {
                        uint32_t a[2][4][4];
#pragma unroll
                        for (int p = 0; p < 2; p++) {
                            uint32_t ab = base + (k * 2 + p) * A_TILE + aoff + s * 32;
#pragma unroll
                            for (int mt = 0; mt < 4; mt++)
                                LDSM_X4(a[p][mt], ab + mt * (16 * ROWB));
                        }
                        uint32_t bb[2][4][2];
#pragma unroll
                        for (int p = 0; p < 2; p++) {
                            uint32_t bbs = base + 6 * A_TILE + p * B_TILE + boff + k * ROWB + s * 32;
#pragma unroll
                            for (int nt = 0; nt < 4; nt++)
                                LDSM_X2(bb[p][nt], bbs + nt * (8 * ROWB));
                        }
#pragma unroll
                        for (int mt = 0; mt < 4; mt++)
#pragma unroll
                            for (int nt = 0; nt < 4; nt++) {
                                MMA(acc[mt][nt], a[0][mt], bb[0][nt]);  // hi*hi
                                MMA(acc[mt][nt], a[0][mt], bb[1][nt]);  // hi*lo
                                MMA(acc[mt][nt], a[1][mt], bb[0][nt]);  // lo*hi
                            }
                    }
                }
                __syncwarp();
                if (lane == 0) MBAR_ARRIVE(sb + 16 + st * 8);
            }
        }

        // ---- epilogue: scale by CONV_SCALE*demod, store ----
        int g = lane >> 2, cg = lane & 3;
        int o_base = ot * 128 + wo * 64;
        int t_base = tt * 128 + wt * 32;
#pragma unroll
        for (int mt = 0; mt < 4; mt++) {
            int o0 = o_base + mt * 16 + g;
            float s0 = CONV_SCALE * g_demod[b * COUT + o0];
            float s1 = CONV_SCALE * g_demod[b * COUT + o0 + 8];
            float* p0 = out + ((size_t)(b * COUT + o0)) * T_ + t_base + cg * 2;
            float* p1 = p0 + 8 * T_;
#pragma unroll
            for (int nt = 0; nt < 4; nt++) {
                float2 v0 = make_float2(acc[mt][nt][0] * s0, acc[mt][nt][1] * s0);
                float2 v1 = make_float2(acc[mt][nt][2] * s1, acc[mt][nt][3] * s1);
                *(float2*)(p0 + nt * 8) = v0;
                *(float2*)(p1 + nt * 8) = v1;
            }
        }
    }
}

// ---------------- launch ----------------
extern "C" void kernel_launch(void* const* d_in, const int* in_sizes, int n_in,
                              void* d_out, int out_size)
{
    const float* x       = (const float*)d_in[0];
    const float* c_src   = (const float*)d_in[1];
    const float* c_trg   = (const float*)d_in[2];
    const float* style_w = (const float*)d_in[3];
    const float* style_b = (const float*)d_in[4];
    const float* weight  = (const float*)d_in[5];
    float* out = (float*)d_out;

    cudaFuncSetAttribute(gemm_kernel, cudaFuncAttributeMaxDynamicSharedMemorySize, SMEM_TOTAL);

    style_kernel<<<B_, 512>>>(c_src, c_trg, style_w, style_b);
    prepw_kernel<<<(KW * COUT * CIN + 255) / 256, 256>>>(weight);
    demod_kernel<<<COUT, 256>>>(weight);
    prepx_kernel<<<dim3(NCH, 16, B_), 256>>>(x);
    gemm_kernel<<<dim3(16, 4, B_), 288, SMEM_TOTAL>>>(out);
}

// round 9
// speedup vs baseline: 3.6833x; 1.3063x over previous
#include <cuda_runtime.h>
#include <cuda_fp16.h>
#include <math.h>
#include <stdint.h>

#define B_      16
#define CIN     512
#define COUT    512
#define T_      2048
#define KW      3
#define LIN_SCALE  0.0625f
#define CONV_SCALE 1.4731391274719738e-2f
#define CONV_SCALE2 (1.0f/4608.0f)

#define NCH     16                 // K chunks (512 / 32)
#define XROWS   136                // B tile rows: t0-1 .. t0+134
#define ROWB    80                 // padded row stride (5*16B -> conflict-free ldmatrix)
#define A_TILE  (128 * ROWB)       // 10240 B
#define B_TILE  (XROWS * ROWB)     // 10880 B
#define STAGE   (6 * A_TILE + B_TILE)       // 72320 B
#define NSTG    2
#define SMEM_TOTAL (1024 + NSTG * STAGE)    // 145664 B

// ---- device scratch (allocation-free rule) ----
__device__ float g_s[B_ * CIN];
__device__ float g_demod[B_ * COUT];
// W images (fp16 hi/lo): [((k*2+p)*4 + ot)*16 + ch] tiles of 128 x 80B  (~3.9 MB)
__device__ __align__(1024) char g_Wimg[3 * 2 * 4 * NCH * A_TILE];
// X images (fp16): [(b*16+tt)*16 + ch] tiles of 136 x 80B               (~44.6 MB)
__device__ __align__(1024) char g_Ximg[(size_t)B_ * 16 * NCH * B_TILE];

// ---------------- PTX helpers (compute_103-safe) ----------------
__device__ __forceinline__ uint32_t smem_u32(const void* p) {
    uint32_t a;
    asm("{ .reg .u64 t; cvta.to.shared.u64 t, %1; cvt.u32.u64 %0, t; }" : "=r"(a) : "l"(p));
    return a;
}
__device__ __forceinline__ uint32_t elect_one() {
    uint32_t p;
    asm volatile("{ .reg .pred p; elect.sync _|p, 0xFFFFFFFF; selp.b32 %0,1,0,p; }" : "=r"(p));
    return p;
}
#define MBAR_INIT(a, n) \
    asm volatile("mbarrier.init.shared.b64 [%0], %1;" :: "r"(a), "r"((uint32_t)(n)) : "memory")
#define MBAR_EXPECT_TX(a, n) \
    asm volatile("mbarrier.arrive.expect_tx.shared.b64 _, [%0], %1;" :: "r"(a), "r"((uint32_t)(n)) : "memory")
#define MBAR_ARRIVE(a) \
    asm volatile("mbarrier.arrive.shared.b64 _, [%0];" :: "r"(a) : "memory")
#define MBAR_WAIT(a, ph) do {                                                  \
    uint32_t _m = (a), _p = (ph), _d;                                          \
    asm volatile("{ .reg .pred p; mbarrier.try_wait.parity.acquire.cta.shared::cta.b64 p, [%1], %2; selp.b32 %0,1,0,p; }" \
                 : "=r"(_d) : "r"(_m), "r"(_p) : "memory");                    \
    if (!_d) {                                                                 \
        asm volatile("{ .reg .pred P1; WL%=: mbarrier.try_wait.parity.acquire.cta.shared::cta.b64 P1, [%0], %1, 0x989680; @P1 bra.uni WD%=; bra.uni WL%=; WD%=: }" \
                     :: "r"(_m), "r"(_p) : "memory");                          \
    } } while (0)
#define BULK_CP(dst, src, nb, mb)                                              \
    asm volatile("cp.async.bulk.shared::cta.global.mbarrier::complete_tx::bytes [%0], [%1], %2, [%3];" \
                 :: "r"((uint32_t)(dst)), "l"(src), "r"((uint32_t)(nb)), "r"((uint32_t)(mb)) : "memory")

#define LDSM_X4(r, addr) \
    asm volatile("ldmatrix.sync.aligned.m8n8.x4.shared.b16 {%0,%1,%2,%3}, [%4];" \
        : "=r"((r)[0]), "=r"((r)[1]), "=r"((r)[2]), "=r"((r)[3]) : "r"(addr))
#define LDSM_X2(r, addr) \
    asm volatile("ldmatrix.sync.aligned.m8n8.x2.shared.b16 {%0,%1}, [%2];" \
        : "=r"((r)[0]), "=r"((r)[1]) : "r"(addr))
#define MMA(c, a, b)                                                           \
    asm volatile("mma.sync.aligned.m16n8k16.row.col.f32.f16.f16.f32 "          \
        "{%0,%1,%2,%3}, {%4,%5,%6,%7}, {%8,%9}, {%0,%1,%2,%3};"                \
        : "+f"((c)[0]), "+f"((c)[1]), "+f"((c)[2]), "+f"((c)[3])               \
        : "r"((a)[0]), "r"((a)[1]), "r"((a)[2]), "r"((a)[3]),                  \
          "r"((b)[0]), "r"((b)[1]))

// ---------------- prep kernels ----------------
__global__ void style_kernel(const float* __restrict__ c_src, const float* __restrict__ c_trg,
                             const float* __restrict__ style_w, const float* __restrict__ style_b)
{
    int b = blockIdx.x, i = threadIdx.x;
    __shared__ float c[256];
    if (i < 128)      c[i] = c_src[b * 128 + i];
    else if (i < 256) c[i] = c_trg[b * 128 + (i - 128)];
    __syncthreads();
    const float* row = style_w + (size_t)i * 256;
    float acc = 0.f;
#pragma unroll 8
    for (int j = 0; j < 256; j++) acc += row[j] * c[j];
    g_s[b * CIN + i] = style_b[i] + LIN_SCALE * acc;
}

__global__ void demod_kernel(const float* __restrict__ weight)
{
    int o = blockIdx.x, tid = threadIdx.x;
    float acc[B_];
#pragma unroll
    for (int b = 0; b < B_; b++) acc[b] = 0.f;
    for (int i = tid; i < CIN; i += 256) {
        const float* wp = weight + (size_t)o * (CIN * KW) + i * KW;
        float w0 = wp[0], w1 = wp[1], w2 = wp[2];
        float wsq = w0*w0 + w1*w1 + w2*w2;
#pragma unroll
        for (int b = 0; b < B_; b++) { float sv = g_s[b * CIN + i]; acc[b] += wsq * sv * sv; }
    }
#pragma unroll
    for (int b = 0; b < B_; b++)
#pragma unroll
        for (int off = 16; off; off >>= 1)
            acc[b] += __shfl_down_sync(0xffffffffu, acc[b], off);
    __shared__ float red[8][B_];
    int lane = tid & 31, warp = tid >> 5;
    if (lane == 0)
#pragma unroll
        for (int b = 0; b < B_; b++) red[warp][b] = acc[b];
    __syncthreads();
    if (tid < B_) {
        float t = 0.f;
#pragma unroll
        for (int w = 0; w < 8; w++) t += red[w][tid];
        g_demod[tid * COUT + o] = rsqrtf(CONV_SCALE2 * t + 1e-8f);
    }
}

// weight[o][i][k] -> A tile images (fp16 hi/lo split), rows=o (80B), cols=i
__global__ void prepw_kernel(const float* __restrict__ weight)
{
    int idx = blockIdx.x * 256 + threadIdx.x;
    if (idx >= KW * COUT * CIN) return;
    int i = idx & (CIN - 1);
    int o = (idx >> 9) & (COUT - 1);
    int k = idx >> 18;
    float v = weight[((size_t)o * CIN + i) * KW + k];
    __half hh = __float2half_rn(v);
    __half hl = __float2half_rn(v - __half2float(hh));
    int ot = o >> 7, row = o & 127, ch = i >> 5, il = i & 31;
    size_t off = (size_t)row * ROWB + il * 2;
    size_t th = (size_t)(((k * 2 + 0) * 4 + ot) * NCH + ch) * A_TILE;
    size_t tl = (size_t)(((k * 2 + 1) * 4 + ot) * NCH + ch) * A_TILE;
    *(__half*)(g_Wimg + th + off) = hh;
    *(__half*)(g_Wimg + tl + off) = hl;
}

// x[b][i][t]*s -> B tile images (fp16), rows=t (t0-1..t0+134, 80B), cols=i
__global__ void prepx_kernel(const float* __restrict__ x)
{
    int ch = blockIdx.x, tt = blockIdx.y, b = blockIdx.z;
    int tid = threadIdx.x, i0 = ch * 32, tbase = tt * 128 - 1;
    __shared__ float tile[32][XROWS + 1];   // pad to 137: conflict-free column reads
    for (int idx = tid; idx < 32 * XROWS; idx += 256) {
        int i = idx / XROWS, r = idx - i * XROWS, tg = tbase + r;
        float v = 0.f;
        if (tg >= 0 && tg < T_)
            v = x[((size_t)b * CIN + i0 + i) * T_ + tg] * g_s[b * CIN + i0 + i];
        tile[i][r] = v;
    }
    __syncthreads();
    char* dst = g_Ximg + (size_t)((b * 16 + tt) * NCH + ch) * B_TILE;
    for (int idx = tid; idx < XROWS * 16; idx += 256) {
        int r = idx >> 4, dp = idx & 15;
        __half2 h = __floats2half2_rn(tile[dp * 2][r], tile[dp * 2 + 1][r]);
        *(__half2*)(dst + r * ROWB + dp * 4) = h;
    }
}

// ---------------- main GEMM kernel ----------------
// 9 warps: 0-7 compute (2x4 warp grid, m64n32 each), 8 = bulk-copy producer.
// Pipeline control flow is byte-identical to the proven Round-5 kernel:
// 2 stages, outer cc 0..7 / inner st 0..1, full[st] at sb+0/8 (count 1, tx),
// empty[st] at sb+16/24 (count 8), phases (cc&1)^1 / cc&1.
__global__ void __launch_bounds__(288, 1)
gemm_kernel(float* __restrict__ out)
{
    extern __shared__ __align__(1024) char smem[];
    const uint32_t sb = smem_u32(smem);
    int tid = threadIdx.x, wid = tid >> 5, lane = tid & 31;
    int tt = blockIdx.x, ot = blockIdx.y, b = blockIdx.z;

    if (tid == 0) {
        MBAR_INIT(sb + 0, 1);  MBAR_INIT(sb + 8, 1);
        MBAR_INIT(sb + 16, 8); MBAR_INIT(sb + 24, 8);
    }
    __syncthreads();

    if (wid == 8) {
        if (elect_one()) {
            for (int cc = 0; cc < 8; cc++) {
#pragma unroll
                for (int st = 0; st < 2; st++) {
                    int c = cc * 2 + st;
                    MBAR_WAIT(sb + 16 + st * 8, (cc & 1) ^ 1);
                    MBAR_EXPECT_TX(sb + st * 8, STAGE);
                    uint32_t dbase = sb + 1024 + st * STAGE;
#pragma unroll
                    for (int kp = 0; kp < 6; kp++) {
                        const char* src = g_Wimg + (size_t)((kp * 4 + ot) * NCH + c) * A_TILE;
                        BULK_CP(dbase + kp * A_TILE, src, A_TILE, sb + st * 8);
                    }
                    {
                        const char* src = g_Ximg + (size_t)((b * 16 + tt) * NCH + c) * B_TILE;
                        BULK_CP(dbase + 6 * A_TILE, src, B_TILE, sb + st * 8);
                    }
                }
            }
        }
    } else {
        int wo = wid >> 2;          // 0..1  (o half)
        int wt = wid & 3;           // 0..3  (t quarter)
        float acc[4][4][4];
#pragma unroll
        for (int mt = 0; mt < 4; mt++)
#pragma unroll
            for (int nt = 0; nt < 4; nt++)
#pragma unroll
                for (int e = 0; e < 4; e++) acc[mt][nt][e] = 0.f;

        const uint32_t aoff = (uint32_t)((wo * 64 + (lane & 15)) * ROWB + (lane >> 4) * 16);
        const int lr = lane & 15;
        const uint32_t boff = (uint32_t)((wt * 32 + (lr & 7)) * ROWB + (lr >> 3) * 16);

        for (int cc = 0; cc < 8; cc++) {
#pragma unroll
            for (int st = 0; st < 2; st++) {
                MBAR_WAIT(sb + st * 8, cc & 1);
                const uint32_t base = sb + 1024 + st * STAGE;
#pragma unroll
                for (int s = 0; s < 2; s++) {
#pragma unroll
                    for (int k = 0; k < 3; k++) {
                        uint32_t a[2][4][4];
#pragma unroll
                        for (int p = 0; p < 2; p++) {
                            uint32_t ab = base + (k * 2 + p) * A_TILE + aoff + s * 32;
#pragma unroll
                            for (int mt = 0; mt < 4; mt++)
                                LDSM_X4(a[p][mt], ab + mt * (16 * ROWB));
                        }
                        uint32_t bb[4][2];
                        {
                            uint32_t bbs = base + 6 * A_TILE + boff + k * ROWB + s * 32;
#pragma unroll
                            for (int nt = 0; nt < 4; nt++)
                                LDSM_X2(bb[nt], bbs + nt * (8 * ROWB));
                        }
#pragma unroll
                        for (int mt = 0; mt < 4; mt++)
#pragma unroll
                            for (int nt = 0; nt < 4; nt++) {
                                MMA(acc[mt][nt], a[0][mt], bb[nt]);  // Whi * X
                                MMA(acc[mt][nt], a[1][mt], bb[nt]);  // Wlo * X
                            }
                    }
                }
                __syncwarp();
                if (lane == 0) MBAR_ARRIVE(sb + 16 + st * 8);
            }
        }

        // ---- epilogue: scale by CONV_SCALE*demod, store ----
        int g = lane >> 2, cg = lane & 3;
        int o_base = ot * 128 + wo * 64;
        int t_base = tt * 128 + wt * 32;
#pragma unroll
        for (int mt = 0; mt < 4; mt++) {
            int o0 = o_base + mt * 16 + g;
            float s0 = CONV_SCALE * g_demod[b * COUT + o0];
            float s1 = CONV_SCALE * g_demod[b * COUT + o0 + 8];
            float* p0 = out + ((size_t)(b * COUT + o0)) * T_ + t_base + cg * 2;
            float* p1 = p0 + 8 * T_;
#pragma unroll
            for (int nt = 0; nt < 4; nt++) {
                float2 v0 = make_float2(acc[mt][nt][0] * s0, acc[mt][nt][1] * s0);
                float2 v1 = make_float2(acc[mt][nt][2] * s1, acc[mt][nt][3] * s1);
                *(float2*)(p0 + nt * 8) = v0;
                *(float2*)(p1 + nt * 8) = v1;
            }
        }
    }
}

// ---------------- launch ----------------
extern "C" void kernel_launch(void* const* d_in, const int* in_sizes, int n_in,
                              void* d_out, int out_size)
{
    const float* x       = (const float*)d_in[0];
    const float* c_src   = (const float*)d_in[1];
    const float* c_trg   = (const float*)d_in[2];
    const float* style_w = (const float*)d_in[3];
    const float* style_b = (const float*)d_in[4];
    const float* weight  = (const float*)d_in[5];
    float* out = (float*)d_out;

    cudaFuncSetAttribute(gemm_kernel, cudaFuncAttributeMaxDynamicSharedMemorySize, SMEM_TOTAL);

    style_kernel<<<B_, 512>>>(c_src, c_trg, style_w, style_b);
    prepw_kernel<<<(KW * COUT * CIN + 255) / 256, 256>>>(weight);
    demod_kernel<<<COUT, 256>>>(weight);
    prepx_kernel<<<dim3(NCH, 16, B_), 256>>>(x);
    gemm_kernel<<<dim3(16, 4, B_), 288, SMEM_TOTAL>>>(out);
}

// round 10
// speedup vs baseline: 5.0895x; 1.3818x over previous
#include <cuda_runtime.h>
#include <cuda_fp16.h>
#include <math.h>
#include <stdint.h>

#define B_      16
#define CIN     512
#define COUT    512
#define T_      2048
#define KW      3
#define LIN_SCALE  0.0625f
#define CONV_SCALE 1.4731391274719738e-2f
#define CONV_SCALE2 (1.0f/4608.0f)

#define NCH     16                 // K chunks (512 / 32)
#define XROWS   136                // B tile rows: t0-1 .. t0+134
#define ROWB    80                 // padded row stride (5*16B -> conflict-free ldmatrix)
#define A_TILE  (128 * ROWB)       // 10240 B
#define B_TILE  (XROWS * ROWB)     // 10880 B
#define STAGE   (3 * A_TILE + B_TILE)       // 41600 B
#define NSTG    2
#define SMEM_TOTAL (1024 + NSTG * STAGE)    // 84224 B

// ---- device scratch (allocation-free rule) ----
__device__ float g_s[B_ * CIN];
__device__ float g_demod[B_ * COUT];
// W images (fp16): [(k*4 + ot)*16 + ch] tiles of 128 x 80B   (~2 MB)
__device__ __align__(1024) char g_Wimg[3 * 4 * NCH * A_TILE];
// X images (fp16): [(b*16+tt)*16 + ch] tiles of 136 x 80B    (~44.6 MB)
__device__ __align__(1024) char g_Ximg[(size_t)B_ * 16 * NCH * B_TILE];

// ---------------- PTX helpers (compute_103-safe) ----------------
__device__ __forceinline__ uint32_t smem_u32(const void* p) {
    uint32_t a;
    asm("{ .reg .u64 t; cvta.to.shared.u64 t, %1; cvt.u32.u64 %0, t; }" : "=r"(a) : "l"(p));
    return a;
}
__device__ __forceinline__ uint32_t elect_one() {
    uint32_t p;
    asm volatile("{ .reg .pred p; elect.sync _|p, 0xFFFFFFFF; selp.b32 %0,1,0,p; }" : "=r"(p));
    return p;
}
#define MBAR_INIT(a, n) \
    asm volatile("mbarrier.init.shared.b64 [%0], %1;" :: "r"(a), "r"((uint32_t)(n)) : "memory")
#define MBAR_EXPECT_TX(a, n) \
    asm volatile("mbarrier.arrive.expect_tx.shared.b64 _, [%0], %1;" :: "r"(a), "r"((uint32_t)(n)) : "memory")
#define MBAR_ARRIVE(a) \
    asm volatile("mbarrier.arrive.shared.b64 _, [%0];" :: "r"(a) : "memory")
#define MBAR_WAIT(a, ph) do {                                                  \
    uint32_t _m = (a), _p = (ph), _d;                                          \
    asm volatile("{ .reg .pred p; mbarrier.try_wait.parity.acquire.cta.shared::cta.b64 p, [%1], %2; selp.b32 %0,1,0,p; }" \
                 : "=r"(_d) : "r"(_m), "r"(_p) : "memory");                    \
    if (!_d) {                                                                 \
        asm volatile("{ .reg .pred P1; WL%=: mbarrier.try_wait.parity.acquire.cta.shared::cta.b64 P1, [%0], %1, 0x989680; @P1 bra.uni WD%=; bra.uni WL%=; WD%=: }" \
                     :: "r"(_m), "r"(_p) : "memory");                          \
    } } while (0)
#define BULK_CP(dst, src, nb, mb)                                              \
    asm volatile("cp.async.bulk.shared::cta.global.mbarrier::complete_tx::bytes [%0], [%1], %2, [%3];" \
                 :: "r"((uint32_t)(dst)), "l"(src), "r"((uint32_t)(nb)), "r"((uint32_t)(mb)) : "memory")

#define LDSM_X4(r, addr) \
    asm volatile("ldmatrix.sync.aligned.m8n8.x4.shared.b16 {%0,%1,%2,%3}, [%4];" \
        : "=r"((r)[0]), "=r"((r)[1]), "=r"((r)[2]), "=r"((r)[3]) : "r"(addr))
#define LDSM_X2(r, addr) \
    asm volatile("ldmatrix.sync.aligned.m8n8.x2.shared.b16 {%0,%1}, [%2];" \
        : "=r"((r)[0]), "=r"((r)[1]) : "r"(addr))
#define MMA(c, a, b)                                                           \
    asm volatile("mma.sync.aligned.m16n8k16.row.col.f32.f16.f16.f32 "          \
        "{%0,%1,%2,%3}, {%4,%5,%6,%7}, {%8,%9}, {%0,%1,%2,%3};"                \
        : "+f"((c)[0]), "+f"((c)[1]), "+f"((c)[2]), "+f"((c)[3])               \
        : "r"((a)[0]), "r"((a)[1]), "r"((a)[2]), "r"((a)[3]),                  \
          "r"((b)[0]), "r"((b)[1]))

// ---------------- prep kernels ----------------
__global__ void style_kernel(const float* __restrict__ c_src, const float* __restrict__ c_trg,
                             const float* __restrict__ style_w, const float* __restrict__ style_b)
{
    int b = blockIdx.x, i = threadIdx.x;
    __shared__ float c[256];
    if (i < 128)      c[i] = c_src[b * 128 + i];
    else if (i < 256) c[i] = c_trg[b * 128 + (i - 128)];
    __syncthreads();
    const float* row = style_w + (size_t)i * 256;
    float acc = 0.f;
#pragma unroll 8
    for (int j = 0; j < 256; j++) acc += row[j] * c[j];
    g_s[b * CIN + i] = style_b[i] + LIN_SCALE * acc;
}

__global__ void demod_kernel(const float* __restrict__ weight)
{
    int o = blockIdx.x, tid = threadIdx.x;
    float acc[B_];
#pragma unroll
    for (int b = 0; b < B_; b++) acc[b] = 0.f;
    for (int i = tid; i < CIN; i += 256) {
        const float* wp = weight + (size_t)o * (CIN * KW) + i * KW;
        float w0 = wp[0], w1 = wp[1], w2 = wp[2];
        float wsq = w0*w0 + w1*w1 + w2*w2;
#pragma unroll
        for (int b = 0; b < B_; b++) { float sv = g_s[b * CIN + i]; acc[b] += wsq * sv * sv; }
    }
#pragma unroll
    for (int b = 0; b < B_; b++)
#pragma unroll
        for (int off = 16; off; off >>= 1)
            acc[b] += __shfl_down_sync(0xffffffffu, acc[b], off);
    __shared__ float red[8][B_];
    int lane = tid & 31, warp = tid >> 5;
    if (lane == 0)
#pragma unroll
        for (int b = 0; b < B_; b++) red[warp][b] = acc[b];
    __syncthreads();
    if (tid < B_) {
        float t = 0.f;
#pragma unroll
        for (int w = 0; w < 8; w++) t += red[w][tid];
        g_demod[tid * COUT + o] = rsqrtf(CONV_SCALE2 * t + 1e-8f);
    }
}

// weight[o][i][k] -> A tile images (fp16), rows=o (80B), cols=i
__global__ void prepw_kernel(const float* __restrict__ weight)
{
    int idx = blockIdx.x * 256 + threadIdx.x;
    if (idx >= KW * COUT * CIN) return;
    int i = idx & (CIN - 1);
    int o = (idx >> 9) & (COUT - 1);
    int k = idx >> 18;
    float v = weight[((size_t)o * CIN + i) * KW + k];
    __half hh = __float2half_rn(v);
    int ot = o >> 7, row = o & 127, ch = i >> 5, il = i & 31;
    size_t off = (size_t)row * ROWB + il * 2;
    size_t th = (size_t)((k * 4 + ot) * NCH + ch) * A_TILE;
    *(__half*)(g_Wimg + th + off) = hh;
}

// x[b][i][t]*s -> B tile images (fp16), rows=t (t0-1..t0+134, 80B), cols=i
__global__ void prepx_kernel(const float* __restrict__ x)
{
    int ch = blockIdx.x, tt = blockIdx.y, b = blockIdx.z;
    int tid = threadIdx.x, i0 = ch * 32, tbase = tt * 128 - 1;
    __shared__ float tile[32][XROWS + 1];   // pad to 137: conflict-free column reads
    for (int idx = tid; idx < 32 * XROWS; idx += 256) {
        int i = idx / XROWS, r = idx - i * XROWS, tg = tbase + r;
        float v = 0.f;
        if (tg >= 0 && tg < T_)
            v = x[((size_t)b * CIN + i0 + i) * T_ + tg] * g_s[b * CIN + i0 + i];
        tile[i][r] = v;
    }
    __syncthreads();
    char* dst = g_Ximg + (size_t)((b * 16 + tt) * NCH + ch) * B_TILE;
    for (int idx = tid; idx < XROWS * 16; idx += 256) {
        int r = idx >> 4, dp = idx & 15;
        __half2 h = __floats2half2_rn(tile[dp * 2][r], tile[dp * 2 + 1][r]);
        *(__half2*)(dst + r * ROWB + dp * 4) = h;
    }
}

// ---------------- main GEMM kernel ----------------
// 9 warps: 0-7 compute (2x4 warp grid, m64n32 each), 8 = bulk-copy producer.
// Pipeline control flow identical to the proven Round-5/9 kernel:
// 2 stages, outer cc 0..7 / inner st 0..1, full[st] at sb+0/8 (count 1, tx),
// empty[st] at sb+16/24 (count 8), phases (cc&1)^1 / cc&1.
__global__ void __launch_bounds__(288, 1)
gemm_kernel(float* __restrict__ out)
{
    extern __shared__ __align__(1024) char smem[];
    const uint32_t sb = smem_u32(smem);
    int tid = threadIdx.x, wid = tid >> 5, lane = tid & 31;
    int tt = blockIdx.x, ot = blockIdx.y, b = blockIdx.z;

    if (tid == 0) {
        MBAR_INIT(sb + 0, 1);  MBAR_INIT(sb + 8, 1);
        MBAR_INIT(sb + 16, 8); MBAR_INIT(sb + 24, 8);
    }
    __syncthreads();

    if (wid == 8) {
        if (elect_one()) {
            for (int cc = 0; cc < 8; cc++) {
#pragma unroll
                for (int st = 0; st < 2; st++) {
                    int c = cc * 2 + st;
                    MBAR_WAIT(sb + 16 + st * 8, (cc & 1) ^ 1);
                    MBAR_EXPECT_TX(sb + st * 8, STAGE);
                    uint32_t dbase = sb + 1024 + st * STAGE;
#pragma unroll
                    for (int k = 0; k < 3; k++) {
                        const char* src = g_Wimg + (size_t)((k * 4 + ot) * NCH + c) * A_TILE;
                        BULK_CP(dbase + k * A_TILE, src, A_TILE, sb + st * 8);
                    }
                    {
                        const char* src = g_Ximg + (size_t)((b * 16 + tt) * NCH + c) * B_TILE;
                        BULK_CP(dbase + 3 * A_TILE, src, B_TILE, sb + st * 8);
                    }
                }
            }
        }
    } else {
        int wo = wid >> 2;          // 0..1  (o half)
        int wt = wid & 3;           // 0..3  (t quarter)
        float acc[4][4][4];
#pragma unroll
        for (int mt = 0; mt < 4; mt++)
#pragma unroll
            for (int nt = 0; nt < 4; nt++)
#pragma unroll
                for (int e = 0; e < 4; e++) acc[mt][nt][e] = 0.f;

        const uint32_t aoff = (uint32_t)((wo * 64 + (lane & 15)) * ROWB + (lane >> 4) * 16);
        const int lr = lane & 15;
        const uint32_t boff = (uint32_t)((wt * 32 + (lr & 7)) * ROWB + (lr >> 3) * 16);

        for (int cc = 0; cc < 8; cc++) {
#pragma unroll
            for (int st = 0; st < 2; st++) {
                MBAR_WAIT(sb + st * 8, cc & 1);
                const uint32_t base = sb + 1024 + st * STAGE;
#pragma unroll
                for (int s = 0; s < 2; s++) {
#pragma unroll
                    for (int k = 0; k < 3; k++) {
                        uint32_t a[4][4];
                        {
                            uint32_t ab = base + k * A_TILE + aoff + s * 32;
#pragma unroll
                            for (int mt = 0; mt < 4; mt++)
                                LDSM_X4(a[mt], ab + mt * (16 * ROWB));
                        }
                        uint32_t bb[4][2];
                        {
                            uint32_t bbs = base + 3 * A_TILE + boff + k * ROWB + s * 32;
#pragma unroll
                            for (int nt = 0; nt < 4; nt++)
                                LDSM_X2(bb[nt], bbs + nt * (8 * ROWB));
                        }
#pragma unroll
                        for (int mt = 0; mt < 4; mt++)
#pragma unroll
                            for (int nt = 0; nt < 4; nt++)
                                MMA(acc[mt][nt], a[mt], bb[nt]);
                    }
                }
                __syncwarp();
                if (lane == 0) MBAR_ARRIVE(sb + 16 + st * 8);
            }
        }

        // ---- epilogue: scale by CONV_SCALE*demod, store ----
        int g = lane >> 2, cg = lane & 3;
        int o_base = ot * 128 + wo * 64;
        int t_base = tt * 128 + wt * 32;
#pragma unroll
        for (int mt = 0; mt < 4; mt++) {
            int o0 = o_base + mt * 16 + g;
            float s0 = CONV_SCALE * g_demod[b * COUT + o0];
            float s1 = CONV_SCALE * g_demod[b * COUT + o0 + 8];
            float* p0 = out + ((size_t)(b * COUT + o0)) * T_ + t_base + cg * 2;
            float* p1 = p0 + 8 * T_;
#pragma unroll
            for (int nt = 0; nt < 4; nt++) {
                float2 v0 = make_float2(acc[mt][nt][0] * s0, acc[mt][nt][1] * s0);
                float2 v1 = make_float2(acc[mt][nt][2] * s1, acc[mt][nt][3] * s1);
                *(float2*)(p0 + nt * 8) = v0;
                *(float2*)(p1 + nt * 8) = v1;
            }
        }
    }
}

// ---------------- launch ----------------
extern "C" void kernel_launch(void* const* d_in, const int* in_sizes, int n_in,
                              void* d_out, int out_size)
{
    const float* x       = (const float*)d_in[0];
    const float* c_src   = (const float*)d_in[1];
    const float* c_trg   = (const float*)d_in[2];
    const float* style_w = (const float*)d_in[3];
    const float* style_b = (const float*)d_in[4];
    const float* weight  = (const float*)d_in[5];
    float* out = (float*)d_out;

    cudaFuncSetAttribute(gemm_kernel, cudaFuncAttributeMaxDynamicSharedMemorySize, SMEM_TOTAL);

    style_kernel<<<B_, 512>>>(c_src, c_trg, style_w, style_b);
    prepw_kernel<<<(KW * COUT * CIN + 255) / 256, 256>>>(weight);
    demod_kernel<<<COUT, 256>>>(weight);
    prepx_kernel<<<dim3(NCH, 16, B_), 256>>>(x);
    gemm_kernel<<<dim3(16, 4, B_), 288, SMEM_TOTAL>>>(out);
}

// round 11
// speedup vs baseline: 5.1652x; 1.0149x over previous
#include <cuda_runtime.h>
#include <cuda_fp16.h>
#include <math.h>
#include <stdint.h>

#define B_      16
#define CIN     512
#define COUT    512
#define T_      2048
#define KW      3
#define LIN_SCALE  0.0625f
#define CONV_SCALE 1.4731391274719738e-2f
#define CONV_SCALE2 (1.0f/4608.0f)

#define NCH     16                 // K chunks (512 / 32)
#define XROWS   136                // B tile rows: t0-1 .. t0+134
#define ROWB    80                 // padded row stride (5*16B -> conflict-free ldmatrix)
#define A_TILE  (128 * ROWB)       // 10240 B
#define B_TILE  (XROWS * ROWB)     // 10880 B
#define STAGE   (3 * A_TILE + B_TILE)       // 41600 B
#define NSTG    2
#define SMEM_TOTAL (1024 + NSTG * STAGE)    // 84224 B  (2 CTAs/SM fit)

// ---- device scratch (allocation-free rule) ----
__device__ float g_s[B_ * CIN];
__device__ float g_demod[B_ * COUT];
// W images (fp16): [(k*4 + ot)*16 + ch] tiles of 128 x 80B   (~2 MB)
__device__ __align__(1024) char g_Wimg[3 * 4 * NCH * A_TILE];
// X images (fp16): [(b*16+tt)*16 + ch] tiles of 136 x 80B    (~44.6 MB)
__device__ __align__(1024) char g_Ximg[(size_t)B_ * 16 * NCH * B_TILE];

// ---------------- PTX helpers (compute_103-safe) ----------------
__device__ __forceinline__ uint32_t smem_u32(const void* p) {
    uint32_t a;
    asm("{ .reg .u64 t; cvta.to.shared.u64 t, %1; cvt.u32.u64 %0, t; }" : "=r"(a) : "l"(p));
    return a;
}
__device__ __forceinline__ uint32_t elect_one() {
    uint32_t p;
    asm volatile("{ .reg .pred p; elect.sync _|p, 0xFFFFFFFF; selp.b32 %0,1,0,p; }" : "=r"(p));
    return p;
}
#define MBAR_INIT(a, n) \
    asm volatile("mbarrier.init.shared.b64 [%0], %1;" :: "r"(a), "r"((uint32_t)(n)) : "memory")
#define MBAR_EXPECT_TX(a, n) \
    asm volatile("mbarrier.arrive.expect_tx.shared.b64 _, [%0], %1;" :: "r"(a), "r"((uint32_t)(n)) : "memory")
#define MBAR_ARRIVE(a) \
    asm volatile("mbarrier.arrive.shared.b64 _, [%0];" :: "r"(a) : "memory")
#define MBAR_WAIT(a, ph) do {                                                  \
    uint32_t _m = (a), _p = (ph), _d;                                          \
    asm volatile("{ .reg .pred p; mbarrier.try_wait.parity.acquire.cta.shared::cta.b64 p, [%1], %2; selp.b32 %0,1,0,p; }" \
                 : "=r"(_d) : "r"(_m), "r"(_p) : "memory");                    \
    if (!_d) {                                                                 \
        asm volatile("{ .reg .pred P1; WL%=: mbarrier.try_wait.parity.acquire.cta.shared::cta.b64 P1, [%0], %1, 0x989680; @P1 bra.uni WD%=; bra.uni WL%=; WD%=: }" \
                     :: "r"(_m), "r"(_p) : "memory");                          \
    } } while (0)
#define BULK_CP(dst, src, nb, mb)                                              \
    asm volatile("cp.async.bulk.shared::cta.global.mbarrier::complete_tx::bytes [%0], [%1], %2, [%3];" \
                 :: "r"((uint32_t)(dst)), "l"(src), "r"((uint32_t)(nb)), "r"((uint32_t)(mb)) : "memory")

#define LDSM_X4(r, addr) \
    asm volatile("ldmatrix.sync.aligned.m8n8.x4.shared.b16 {%0,%1,%2,%3}, [%4];" \
        : "=r"((r)[0]), "=r"((r)[1]), "=r"((r)[2]), "=r"((r)[3]) : "r"(addr))
#define MMA(c, a, b)                                                           \
    asm volatile("mma.sync.aligned.m16n8k16.row.col.f32.f16.f16.f32 "          \
        "{%0,%1,%2,%3}, {%4,%5,%6,%7}, {%8,%9}, {%0,%1,%2,%3};"                \
        : "+f"((c)[0]), "+f"((c)[1]), "+f"((c)[2]), "+f"((c)[3])               \
        : "r"((a)[0]), "r"((a)[1]), "r"((a)[2]), "r"((a)[3]),                  \
          "r"((b)[0]), "r"((b)[1]))

// ---------------- prep kernels ----------------
__global__ void style_kernel(const float* __restrict__ c_src, const float* __restrict__ c_trg,
                             const float* __restrict__ style_w, const float* __restrict__ style_b)
{
    int b = blockIdx.x, i = threadIdx.x;
    __shared__ float c[256];
    if (i < 128)      c[i] = c_src[b * 128 + i];
    else if (i < 256) c[i] = c_trg[b * 128 + (i - 128)];
    __syncthreads();
    const float* row = style_w + (size_t)i * 256;
    float acc = 0.f;
#pragma unroll 8
    for (int j = 0; j < 256; j++) acc += row[j] * c[j];
    g_s[b * CIN + i] = style_b[i] + LIN_SCALE * acc;
}

__global__ void demod_kernel(const float* __restrict__ weight)
{
    int o = blockIdx.x, tid = threadIdx.x;
    float acc[B_];
#pragma unroll
    for (int b = 0; b < B_; b++) acc[b] = 0.f;
    for (int i = tid; i < CIN; i += 256) {
        const float* wp = weight + (size_t)o * (CIN * KW) + i * KW;
        float w0 = wp[0], w1 = wp[1], w2 = wp[2];
        float wsq = w0*w0 + w1*w1 + w2*w2;
#pragma unroll
        for (int b = 0; b < B_; b++) { float sv = g_s[b * CIN + i]; acc[b] += wsq * sv * sv; }
    }
#pragma unroll
    for (int b = 0; b < B_; b++)
#pragma unroll
        for (int off = 16; off; off >>= 1)
            acc[b] += __shfl_down_sync(0xffffffffu, acc[b], off);
    __shared__ float red[8][B_];
    int lane = tid & 31, warp = tid >> 5;
    if (lane == 0)
#pragma unroll
        for (int b = 0; b < B_; b++) red[warp][b] = acc[b];
    __syncthreads();
    if (tid < B_) {
        float t = 0.f;
#pragma unroll
        for (int w = 0; w < 8; w++) t += red[w][tid];
        g_demod[tid * COUT + o] = rsqrtf(CONV_SCALE2 * t + 1e-8f);
    }
}

// weight[o][i][k] -> A tile images (fp16), rows=o (80B), cols=i
__global__ void prepw_kernel(const float* __restrict__ weight)
{
    int idx = blockIdx.x * 256 + threadIdx.x;
    if (idx >= KW * COUT * CIN) return;
    int i = idx & (CIN - 1);
    int o = (idx >> 9) & (COUT - 1);
    int k = idx >> 18;
    float v = weight[((size_t)o * CIN + i) * KW + k];
    __half hh = __float2half_rn(v);
    int ot = o >> 7, row = o & 127, ch = i >> 5, il = i & 31;
    size_t off = (size_t)row * ROWB + il * 2;
    size_t th = (size_t)((k * 4 + ot) * NCH + ch) * A_TILE;
    *(__half*)(g_Wimg + th + off) = hh;
}

// x[b][i][t]*s -> B tile images (fp16). 2 chunks (64 i) per block for ILP.
__global__ void prepx_kernel(const float* __restrict__ x)
{
    int chp = blockIdx.x, tt = blockIdx.y, b = blockIdx.z;
    int tid = threadIdx.x, i0 = chp * 64, tbase = tt * 128 - 1;
    __shared__ float tile[64][XROWS + 1];   // 137 cols
    for (int idx = tid; idx < 64 * XROWS; idx += 256) {
        int i = idx / XROWS, r = idx - i * XROWS, tg = tbase + r;
        float v = 0.f;
        if (tg >= 0 && tg < T_)
            v = x[((size_t)b * CIN + i0 + i) * T_ + tg] * g_s[b * CIN + i0 + i];
        tile[i][r] = v;
    }
    __syncthreads();
    char* d0 = g_Ximg + (size_t)((b * 16 + tt) * NCH + chp * 2) * B_TILE;
    for (int idx = tid; idx < XROWS * 32; idx += 256) {
        int r = idx >> 5, dp = idx & 31;           // dp: 32 i-pairs over 64 i
        __half2 h = __floats2half2_rn(tile[dp * 2][r], tile[dp * 2 + 1][r]);
        char* dst = d0 + (size_t)(dp >> 4) * B_TILE;   // chunk select
        *(__half2*)(dst + r * ROWB + (dp & 15) * 4) = h;
    }
}

// ---------------- main GEMM kernel ----------------
// 9 warps: 0-7 compute (2x4 warp grid, m64n32 each), 8 = bulk-copy producer.
// Pipeline control flow identical to the proven Round-5/9/10 kernel.
__global__ void __launch_bounds__(288, 2)
gemm_kernel(float* __restrict__ out)
{
    extern __shared__ __align__(1024) char smem[];
    const uint32_t sb = smem_u32(smem);
    int tid = threadIdx.x, wid = tid >> 5, lane = tid & 31;
    int tt = blockIdx.x, ot = blockIdx.y, b = blockIdx.z;

    if (tid == 0) {
        MBAR_INIT(sb + 0, 1);  MBAR_INIT(sb + 8, 1);
        MBAR_INIT(sb + 16, 8); MBAR_INIT(sb + 24, 8);
    }
    __syncthreads();

    if (wid == 8) {
        if (elect_one()) {
            for (int cc = 0; cc < 8; cc++) {
#pragma unroll
                for (int st = 0; st < 2; st++) {
                    int c = cc * 2 + st;
                    MBAR_WAIT(sb + 16 + st * 8, (cc & 1) ^ 1);
                    MBAR_EXPECT_TX(sb + st * 8, STAGE);
                    uint32_t dbase = sb + 1024 + st * STAGE;
#pragma unroll
                    for (int k = 0; k < 3; k++) {
                        const char* src = g_Wimg + (size_t)((k * 4 + ot) * NCH + c) * A_TILE;
                        BULK_CP(dbase + k * A_TILE, src, A_TILE, sb + st * 8);
                    }
                    {
                        const char* src = g_Ximg + (size_t)((b * 16 + tt) * NCH + c) * B_TILE;
                        BULK_CP(dbase + 3 * A_TILE, src, B_TILE, sb + st * 8);
                    }
                }
            }
        }
    } else {
        int wo = wid >> 2;          // 0..1  (o half)
        int wt = wid & 3;           // 0..3  (t quarter)
        float acc[4][4][4];
#pragma unroll
        for (int mt = 0; mt < 4; mt++)
#pragma unroll
            for (int nt = 0; nt < 4; nt++)
#pragma unroll
                for (int e = 0; e < 4; e++) acc[mt][nt][e] = 0.f;

        // A ldmatrix per-lane offset (rows = o)
        const uint32_t aoff = (uint32_t)((wo * 64 + (lane & 15)) * ROWB + (lane >> 4) * 16);
        // B ldmatrix X4 per-lane offset: m = lane>>3 selects (nt-pair half, k-half):
        //   row block = (m>>1)*8, col half = (m&1)*16
        const uint32_t boff4 = (uint32_t)((wt * 32 + ((lane >> 4) & 1) * 8 + (lane & 7)) * ROWB
                                          + ((lane >> 3) & 1) * 16);

        for (int cc = 0; cc < 8; cc++) {
#pragma unroll
            for (int st = 0; st < 2; st++) {
                MBAR_WAIT(sb + st * 8, cc & 1);
                const uint32_t base = sb + 1024 + st * STAGE;
#pragma unroll
                for (int s = 0; s < 2; s++) {
#pragma unroll
                    for (int k = 0; k < 3; k++) {
                        uint32_t a[4][4];
                        {
                            uint32_t ab = base + k * A_TILE + aoff + s * 32;
#pragma unroll
                            for (int mt = 0; mt < 4; mt++)
                                LDSM_X4(a[mt], ab + mt * (16 * ROWB));
                        }
                        uint32_t bb[2][4];   // [nt-pair][4 regs: nt0{k0,k1}, nt1{k0,k1}]
                        {
                            uint32_t bbs = base + 3 * A_TILE + boff4 + k * ROWB + s * 32;
                            LDSM_X4(bb[0], bbs);
                            LDSM_X4(bb[1], bbs + 16 * ROWB);
                        }
#pragma unroll
                        for (int mt = 0; mt < 4; mt++)
#pragma unroll
                            for (int np = 0; np < 2; np++) {
                                MMA(acc[mt][np * 2 + 0], a[mt], (bb[np] + 0));
                                MMA(acc[mt][np * 2 + 1], a[mt], (bb[np] + 2));
                            }
                    }
                }
                __syncwarp();
                if (lane == 0) MBAR_ARRIVE(sb + 16 + st * 8);
            }
        }

        // ---- epilogue: scale by CONV_SCALE*demod, store ----
        int g = lane >> 2, cg = lane & 3;
        int o_base = ot * 128 + wo * 64;
        int t_base = tt * 128 + wt * 32;
#pragma unroll
        for (int mt = 0; mt < 4; mt++) {
            int o0 = o_base + mt * 16 + g;
            float s0 = CONV_SCALE * g_demod[b * COUT + o0];
            float s1 = CONV_SCALE * g_demod[b * COUT + o0 + 8];
            float* p0 = out + ((size_t)(b * COUT + o0)) * T_ + t_base + cg * 2;
            float* p1 = p0 + 8 * T_;
#pragma unroll
            for (int nt = 0; nt < 4; nt++) {
                float2 v0 = make_float2(acc[mt][nt][0] * s0, acc[mt][nt][1] * s0);
                float2 v1 = make_float2(acc[mt][nt][2] * s1, acc[mt][nt][3] * s1);
                *(float2*)(p0 + nt * 8) = v0;
                *(float2*)(p1 + nt * 8) = v1;
            }
        }
    }
}

// ---------------- launch ----------------
extern "C" void kernel_launch(void* const* d_in, const int* in_sizes, int n_in,
                              void* d_out, int out_size)
{
    const float* x       = (const float*)d_in[0];
    const float* c_src   = (const float*)d_in[1];
    const float* c_trg   = (const float*)d_in[2];
    const float* style_w = (const float*)d_in[3];
    const float* style_b = (const float*)d_in[4];
    const float* weight  = (const float*)d_in[5];
    float* out = (float*)d_out;

    cudaFuncSetAttribute(gemm_kernel, cudaFuncAttributeMaxDynamicSharedMemorySize, SMEM_TOTAL);

    style_kernel<<<B_, 512>>>(c_src, c_trg, style_w, style_b);
    prepw_kernel<<<(KW * COUT * CIN + 255) / 256, 256>>>(weight);
    demod_kernel<<<COUT, 256>>>(weight);
    prepx_kernel<<<dim3(8, 16, B_), 256>>>(x);
    gemm_kernel<<<dim3(16, 4, B_), 288, SMEM_TOTAL>>>(out);
}

// round 13
// speedup vs baseline: 5.2594x; 1.0182x over previous
#include <cuda_runtime.h>
#include <cuda_fp16.h>
#include <math.h>
#include <stdint.h>

#define B_      16
#define CIN     512
#define COUT    512
#define T_      2048
#define KW      3
#define LIN_SCALE  0.0625f
#define CONV_SCALE 1.4731391274719738e-2f
#define CONV_SCALE2 (1.0f/4608.0f)

#define NCH     16                 // K chunks (512 / 32)
#define XROWS   136                // B tile rows: t0-1 .. t0+134
#define ROWB    80                 // padded row stride (5*16B -> conflict-free ldmatrix)
#define A_TILE  (128 * ROWB)       // 10240 B
#define B_TILE  (XROWS * ROWB)     // 10880 B
#define STAGE   (3 * A_TILE + B_TILE)       // 41600 B
#define NSTG    2
#define SMEM_TOTAL (1024 + NSTG * STAGE)    // 84224 B  (2 CTAs/SM fit)

// ---- device scratch (allocation-free rule) ----
__device__ float g_s[B_ * CIN];
__device__ float g_demod[B_ * COUT];
// W images (fp16): [(k*4 + ot)*16 + ch] tiles of 128 x 80B   (~2 MB)
__device__ __align__(1024) char g_Wimg[3 * 4 * NCH * A_TILE];
// X images (fp16): [(b*16+tt)*16 + ch] tiles of 136 x 80B    (~44.6 MB)
__device__ __align__(1024) char g_Ximg[(size_t)B_ * 16 * NCH * B_TILE];

// ---------------- PTX helpers (compute_103-safe) ----------------
__device__ __forceinline__ uint32_t smem_u32(const void* p) {
    uint32_t a;
    asm("{ .reg .u64 t; cvta.to.shared.u64 t, %1; cvt.u32.u64 %0, t; }" : "=r"(a) : "l"(p));
    return a;
}
__device__ __forceinline__ uint32_t elect_one() {
    uint32_t p;
    asm volatile("{ .reg .pred p; elect.sync _|p, 0xFFFFFFFF; selp.b32 %0,1,0,p; }" : "=r"(p));
    return p;
}
#define MBAR_INIT(a, n) \
    asm volatile("mbarrier.init.shared.b64 [%0], %1;" :: "r"(a), "r"((uint32_t)(n)) : "memory")
#define MBAR_EXPECT_TX(a, n) \
    asm volatile("mbarrier.arrive.expect_tx.shared.b64 _, [%0], %1;" :: "r"(a), "r"((uint32_t)(n)) : "memory")
#define MBAR_ARRIVE(a) \
    asm volatile("mbarrier.arrive.shared.b64 _, [%0];" :: "r"(a) : "memory")
#define MBAR_WAIT(a, ph) do {                                                  \
    uint32_t _m = (a), _p = (ph), _d;                                          \
    asm volatile("{ .reg .pred p; mbarrier.try_wait.parity.acquire.cta.shared::cta.b64 p, [%1], %2; selp.b32 %0,1,0,p; }" \
                 : "=r"(_d) : "r"(_m), "r"(_p) : "memory");                    \
    if (!_d) {                                                                 \
        asm volatile("{ .reg .pred P1; WL%=: mbarrier.try_wait.parity.acquire.cta.shared::cta.b64 P1, [%0], %1, 0x989680; @P1 bra.uni WD%=; bra.uni WL%=; WD%=: }" \
                     :: "r"(_m), "r"(_p) : "memory");                          \
    } } while (0)
#define BULK_CP(dst, src, nb, mb)                                              \
    asm volatile("cp.async.bulk.shared::cta.global.mbarrier::complete_tx::bytes [%0], [%1], %2, [%3];" \
                 :: "r"((uint32_t)(dst)), "l"(src), "r"((uint32_t)(nb)), "r"((uint32_t)(mb)) : "memory")

#define LDSM_X4(r, addr) \
    asm volatile("ldmatrix.sync.aligned.m8n8.x4.shared.b16 {%0,%1,%2,%3}, [%4];" \
        : "=r"((r)[0]), "=r"((r)[1]), "=r"((r)[2]), "=r"((r)[3]) : "r"(addr))
#define MMA(c, a, b)                                                           \
    asm volatile("mma.sync.aligned.m16n8k16.row.col.f32.f16.f16.f32 "          \
        "{%0,%1,%2,%3}, {%4,%5,%6,%7}, {%8,%9}, {%0,%1,%2,%3};"                \
        : "+f"((c)[0]), "+f"((c)[1]), "+f"((c)[2]), "+f"((c)[3])               \
        : "r"((a)[0]), "r"((a)[1]), "r"((a)[2]), "r"((a)[3]),                  \
          "r"((b)[0]), "r"((b)[1]))

// ---------------- prep kernels ----------------
__global__ void style_kernel(const float* __restrict__ c_src, const float* __restrict__ c_trg,
                             const float* __restrict__ style_w, const float* __restrict__ style_b)
{
    int b = blockIdx.x, i = threadIdx.x;
    __shared__ float c[256];
    if (i < 128)      c[i] = c_src[b * 128 + i];
    else if (i < 256) c[i] = c_trg[b * 128 + (i - 128)];
    __syncthreads();
    const float* row = style_w + (size_t)i * 256;
    float acc = 0.f;
#pragma unroll 8
    for (int j = 0; j < 256; j++) acc += row[j] * c[j];
    g_s[b * CIN + i] = style_b[i] + LIN_SCALE * acc;
}

__global__ void demod_kernel(const float* __restrict__ weight)
{
    int o = blockIdx.x, tid = threadIdx.x;
    float acc[B_];
#pragma unroll
    for (int b = 0; b < B_; b++) acc[b] = 0.f;
    for (int i = tid; i < CIN; i += 256) {
        const float* wp = weight + (size_t)o * (CIN * KW) + i * KW;
        float w0 = wp[0], w1 = wp[1], w2 = wp[2];
        float wsq = w0*w0 + w1*w1 + w2*w2;
#pragma unroll
        for (int b = 0; b < B_; b++) { float sv = g_s[b * CIN + i]; acc[b] += wsq * sv * sv; }
    }
#pragma unroll
    for (int b = 0; b < B_; b++)
#pragma unroll
        for (int off = 16; off; off >>= 1)
            acc[b] += __shfl_down_sync(0xffffffffu, acc[b], off);
    __shared__ float red[8][B_];
    int lane = tid & 31, warp = tid >> 5;
    if (lane == 0)
#pragma unroll
        for (int b = 0; b < B_; b++) red[warp][b] = acc[b];
    __syncthreads();
    if (tid < B_) {
        float t = 0.f;
#pragma unroll
        for (int w = 0; w < 8; w++) t += red[w][tid];
        g_demod[tid * COUT + o] = rsqrtf(CONV_SCALE2 * t + 1e-8f);
    }
}

// weight[o][i][k] -> A tile images (fp16), rows=o (80B), cols=i
__global__ void prepw_kernel(const float* __restrict__ weight)
{
    int idx = blockIdx.x * 256 + threadIdx.x;
    if (idx >= KW * COUT * CIN) return;
    int i = idx & (CIN - 1);
    int o = (idx >> 9) & (COUT - 1);
    int k = idx >> 18;
    float v = weight[((size_t)o * CIN + i) * KW + k];
    __half hh = __float2half_rn(v);
    int ot = o >> 7, row = o & 127, ch = i >> 5, il = i & 31;
    size_t off = (size_t)row * ROWB + il * 2;
    size_t th = (size_t)((k * 4 + ot) * NCH + ch) * A_TILE;
    *(__half*)(g_Wimg + th + off) = hh;
}

// x[b][i][t]*s -> B tile images (fp16), rows=t (t0-1..t0+134, 80B), cols=i
// (proven Round-10 version: 1 chunk per block)
__global__ void prepx_kernel(const float* __restrict__ x)
{
    int ch = blockIdx.x, tt = blockIdx.y, b = blockIdx.z;
    int tid = threadIdx.x, i0 = ch * 32, tbase = tt * 128 - 1;
    __shared__ float tile[32][XROWS + 1];   // pad to 137: conflict-free column reads
    for (int idx = tid; idx < 32 * XROWS; idx += 256) {
        int i = idx / XROWS, r = idx - i * XROWS, tg = tbase + r;
        float v = 0.f;
        if (tg >= 0 && tg < T_)
            v = x[((size_t)b * CIN + i0 + i) * T_ + tg] * g_s[b * CIN + i0 + i];
        tile[i][r] = v;
    }
    __syncthreads();
    char* dst = g_Ximg + (size_t)((b * 16 + tt) * NCH + ch) * B_TILE;
    for (int idx = tid; idx < XROWS * 16; idx += 256) {
        int r = idx >> 4, dp = idx & 15;
        __half2 h = __floats2half2_rn(tile[dp * 2][r], tile[dp * 2 + 1][r]);
        *(__half2*)(dst + r * ROWB + dp * 4) = h;
    }
}

// ---------------- main GEMM kernel ----------------
// 9 warps: 0-7 compute in a 4(o) x 2(t) grid (m32 x n64 each), 8 = producer.
// 4x2 grid cuts per-chunk SMEM reads to 2*A_tile + 4*B_tile (was 4*A + 2*B).
// Pipeline control flow identical to the proven Round-5/9/10 kernel.
__global__ void __launch_bounds__(288, 2)
gemm_kernel(float* __restrict__ out)
{
    extern __shared__ __align__(1024) char smem[];
    const uint32_t sb = smem_u32(smem);
    int tid = threadIdx.x, wid = tid >> 5, lane = tid & 31;
    int tt = blockIdx.x, ot = blockIdx.y, b = blockIdx.z;

    if (tid == 0) {
        MBAR_INIT(sb + 0, 1);  MBAR_INIT(sb + 8, 1);
        MBAR_INIT(sb + 16, 8); MBAR_INIT(sb + 24, 8);
    }
    __syncthreads();

    if (wid == 8) {
        if (elect_one()) {
            for (int cc = 0; cc < 8; cc++) {
#pragma unroll
                for (int st = 0; st < 2; st++) {
                    int c = cc * 2 + st;
                    MBAR_WAIT(sb + 16 + st * 8, (cc & 1) ^ 1);
                    MBAR_EXPECT_TX(sb + st * 8, STAGE);
                    uint32_t dbase = sb + 1024 + st * STAGE;
#pragma unroll
                    for (int k = 0; k < 3; k++) {
                        const char* src = g_Wimg + (size_t)((k * 4 + ot) * NCH + c) * A_TILE;
                        BULK_CP(dbase + k * A_TILE, src, A_TILE, sb + st * 8);
                    }
                    {
                        const char* src = g_Ximg + (size_t)((b * 16 + tt) * NCH + c) * B_TILE;
                        BULK_CP(dbase + 3 * A_TILE, src, B_TILE, sb + st * 8);
                    }
                }
            }
        }
    } else {
        int wo = wid >> 1;          // 0..3  (o quarter, 32 rows)
        int wt = wid & 1;           // 0..1  (t half, 64 cols)
        float acc[2][8][4];
#pragma unroll
        for (int mt = 0; mt < 2; mt++)
#pragma unroll
            for (int nt = 0; nt < 8; nt++)
#pragma unroll
                for (int e = 0; e < 4; e++) acc[mt][nt][e] = 0.f;

        // A ldmatrix per-lane offset (rows = o)
        const uint32_t aoff = (uint32_t)((wo * 32 + (lane & 15)) * ROWB + (lane >> 4) * 16);
        // B ldmatrix X4 per-lane offset (proven R11 mapping): within a 16-row pair
        // block, row = ((lane>>4)&1)*8 + (lane&7), col half = ((lane>>3)&1)*16
        const uint32_t boff4 = (uint32_t)((wt * 64 + ((lane >> 4) & 1) * 8 + (lane & 7)) * ROWB
                                          + ((lane >> 3) & 1) * 16);

        for (int cc = 0; cc < 8; cc++) {
#pragma unroll
            for (int st = 0; st < 2; st++) {
                MBAR_WAIT(sb + st * 8, cc & 1);
                const uint32_t base = sb + 1024 + st * STAGE;
#pragma unroll
                for (int s = 0; s < 2; s++) {
#pragma unroll
                    for (int k = 0; k < 3; k++) {
                        uint32_t a[2][4];
                        {
                            uint32_t ab = base + k * A_TILE + aoff + s * 32;
                            LDSM_X4(a[0], ab);
                            LDSM_X4(a[1], ab + 16 * ROWB);
                        }
                        uint32_t bb[4][4];   // [nt-pair][nt0{k0,k1}, nt1{k0,k1}]
                        {
                            uint32_t bbs = base + 3 * A_TILE + boff4 + k * ROWB + s * 32;
#pragma unroll
                            for (int np = 0; np < 4; np++)
                                LDSM_X4(bb[np], bbs + np * (16 * ROWB));
                        }
#pragma unroll
                        for (int mt = 0; mt < 2; mt++)
#pragma unroll
                            for (int np = 0; np < 4; np++) {
                                MMA(acc[mt][np * 2 + 0], a[mt], (bb[np] + 0));
                                MMA(acc[mt][np * 2 + 1], a[mt], (bb[np] + 2));
                            }
                    }
                }
                __syncwarp();
                if (lane == 0) MBAR_ARRIVE(sb + 16 + st * 8);
            }
        }

        // ---- epilogue: scale by CONV_SCALE*demod, store ----
        int g = lane >> 2, cg = lane & 3;
        int o_base = ot * 128 + wo * 32;
        int t_base = tt * 128 + wt * 64;
#pragma unroll
        for (int mt = 0; mt < 2; mt++) {
            int o0 = o_base + mt * 16 + g;
            float s0 = CONV_SCALE * g_demod[b * COUT + o0];
            float s1 = CONV_SCALE * g_demod[b * COUT + o0 + 8];
            float* p0 = out + ((size_t)(b * COUT + o0)) * T_ + t_base + cg * 2;
            float* p1 = p0 + 8 * T_;
#pragma unroll
            for (int nt = 0; nt < 8; nt++) {
                float2 v0 = make_float2(acc[mt][nt][0] * s0, acc[mt][nt][1] * s0);
                float2 v1 = make_float2(acc[mt][nt][2] * s1, acc[mt][nt][3] * s1);
                *(float2*)(p0 + nt * 8) = v0;
                *(float2*)(p1 + nt * 8) = v1;
            }
        }
    }
}

// ---------------- launch ----------------
extern "C" void kernel_launch(void* const* d_in, const int* in_sizes, int n_in,
                              void* d_out, int out_size)
{
    const float* x       = (const float*)d_in[0];
    const float* c_src   = (const float*)d_in[1];
    const float* c_trg   = (const float*)d_in[2];
    const float* style_w = (const float*)d_in[3];
    const float* style_b = (const float*)d_in[4];
    const float* weight  = (const float*)d_in[5];
    float* out = (float*)d_out;

    cudaFuncSetAttribute(gemm_kernel, cudaFuncAttributeMaxDynamicSharedMemorySize, SMEM_TOTAL);

    style_kernel<<<B_, 512>>>(c_src, c_trg, style_w, style_b);
    prepw_kernel<<<(KW * COUT * CIN + 255) / 256, 256>>>(weight);
    demod_kernel<<<COUT, 256>>>(weight);
    prepx_kernel<<<dim3(NCH, 16, B_), 256>>>(x);
    gemm_kernel<<<dim3(16, 4, B_), 288, SMEM_TOTAL>>>(out);
}